// round 11
// baseline (speedup 1.0000x reference)
#include <cuda_runtime.h>
#include <cuda_bf16.h>
#include <cuda_fp16.h>
#include <cstdint>

#define DM 1024
#define NH 16
#define HD 64
#define BB 2
#define TT 2048
#define MM (BB*TT)   // 4096 rows
#define WSZ ((size_t)DM * DM)

// Scratch. Q/K fp16 hi+lo, V fp16 in [B,H,T,D]; x & weights & attn-out bf16 hi/lo.
__device__ __half g_qh[(size_t)MM * DM];
__device__ __half g_ql[(size_t)MM * DM];
__device__ __half g_kh[(size_t)MM * DM];
__device__ __half g_kl[(size_t)MM * DM];
__device__ __half g_vh[(size_t)MM * DM];
__device__ __nv_bfloat16 g_xh[(size_t)MM * DM];
__device__ __nv_bfloat16 g_xl[(size_t)MM * DM];
__device__ __nv_bfloat16 g_wh[4 * WSZ];
__device__ __nv_bfloat16 g_wl[4 * WSZ];
__device__ __nv_bfloat16 g_ah[(size_t)MM * DM];
__device__ __nv_bfloat16 g_al[(size_t)MM * DM];

__device__ __forceinline__ uint32_t smem_addr_u32(const void* smem_ptr) {
    uint32_t addr;
    asm("{ .reg .u64 tmp; cvta.to.shared.u64 tmp, %1; cvt.u32.u64 %0, tmp; }"
        : "=r"(addr) : "l"(smem_ptr));
    return addr;
}

#define SMEM_SWIZZLE_128B(byte_offset) \
    ((byte_offset) ^ (((byte_offset) >> 3) & 0x70))

__device__ __forceinline__ void cp_async16(uint32_t dst, const void* src) {
    asm volatile("cp.async.cg.shared.global [%0], [%1], 16;"
                 :: "r"(dst), "l"(src));
}
#define CP_COMMIT() asm volatile("cp.async.commit_group;" ::: "memory")

__device__ __forceinline__ void ldmatrix_x4(uint32_t& r0, uint32_t& r1,
                                            uint32_t& r2, uint32_t& r3,
                                            uint32_t addr) {
    asm volatile("ldmatrix.sync.aligned.m8n8.x4.shared.b16 {%0,%1,%2,%3}, [%4];"
                 : "=r"(r0), "=r"(r1), "=r"(r2), "=r"(r3) : "r"(addr));
}

__device__ __forceinline__ void ldmatrix_x4_trans(uint32_t& r0, uint32_t& r1,
                                                  uint32_t& r2, uint32_t& r3,
                                                  uint32_t addr) {
    asm volatile("ldmatrix.sync.aligned.m8n8.x4.trans.shared.b16 {%0,%1,%2,%3}, [%4];"
                 : "=r"(r0), "=r"(r1), "=r"(r2), "=r"(r3) : "r"(addr));
}

__device__ __forceinline__ void mma_bf16(float* d, const uint32_t* a,
                                         uint32_t b0, uint32_t b1) {
    asm volatile(
        "mma.sync.aligned.m16n8k16.row.col.f32.bf16.bf16.f32 "
        "{%0,%1,%2,%3}, {%4,%5,%6,%7}, {%8,%9}, {%0,%1,%2,%3};"
        : "+f"(d[0]), "+f"(d[1]), "+f"(d[2]), "+f"(d[3])
        : "r"(a[0]), "r"(a[1]), "r"(a[2]), "r"(a[3]), "r"(b0), "r"(b1));
}

__device__ __forceinline__ void mma_f16(float* d, const uint32_t* a,
                                        uint32_t b0, uint32_t b1) {
    asm volatile(
        "mma.sync.aligned.m16n8k16.row.col.f32.f16.f16.f32 "
        "{%0,%1,%2,%3}, {%4,%5,%6,%7}, {%8,%9}, {%0,%1,%2,%3};"
        : "+f"(d[0]), "+f"(d[1]), "+f"(d[2]), "+f"(d[3])
        : "r"(a[0]), "r"(a[1]), "r"(a[2]), "r"(a[3]), "r"(b0), "r"(b1));
}

__device__ __forceinline__ uint32_t pack_bf2(__nv_bfloat16 a, __nv_bfloat16 b) {
    return ((uint32_t)__bfloat16_as_ushort(b) << 16) | (uint32_t)__bfloat16_as_ushort(a);
}

__device__ __forceinline__ uint32_t pack_h2(float a, float b) {
    __half2 h = __floats2half2_rn(a, b);
    return *(uint32_t*)&h;
}

// two fp32 -> fp16 hi + fp16 lo packed words
__device__ __forceinline__ void h_split2(float a, float b,
                                         uint32_t& hi, uint32_t& lo) {
    __half ha = __float2half_rn(a), hb = __float2half_rn(b);
    __half2 hh = __halves2half2(ha, hb);
    hi = *(uint32_t*)&hh;
    lo = pack_h2(a - __half2float(ha), b - __half2float(hb));
}

// exp2 on the FMA pipe (no MUFU); rel err ~2.4e-6.
__device__ __forceinline__ float fexp2(float x) {
    x = fmaxf(x, -28.f);
    float t = x + 12582912.f;
    float i = t - 12582912.f;
    float f = x - i;
    float p = 0.0013333558f;
    p = fmaf(p, f, 0.0096181291f);
    p = fmaf(p, f, 0.0555041087f);
    p = fmaf(p, f, 0.2402265069f);
    p = fmaf(p, f, 0.6931471806f);
    p = fmaf(p, f, 1.0f);
    int ei = (int)i;
    return p * __int_as_float((127 + ei) << 23);
}

#define QSCALE (0.125f * 1.4426950408889634f)

// ===========================================================================
// Pre-split x, weights (fp32 -> bf16 hi/lo).
// ===========================================================================
__global__ __launch_bounds__(256)
void split_f32(const float* __restrict__ src, __nv_bfloat16* __restrict__ hi,
               __nv_bfloat16* __restrict__ lo, int n4)
{
    int i = blockIdx.x * blockDim.x + threadIdx.x;
    if (i >= n4) return;
    float4 v = *(const float4*)(src + (size_t)i * 4);
    __nv_bfloat16 h0 = __float2bfloat16_rn(v.x);
    __nv_bfloat16 h1 = __float2bfloat16_rn(v.y);
    __nv_bfloat16 h2 = __float2bfloat16_rn(v.z);
    __nv_bfloat16 h3 = __float2bfloat16_rn(v.w);
    __nv_bfloat16 l0 = __float2bfloat16_rn(v.x - __bfloat162float(h0));
    __nv_bfloat16 l1 = __float2bfloat16_rn(v.y - __bfloat162float(h1));
    __nv_bfloat16 l2 = __float2bfloat16_rn(v.z - __bfloat162float(h2));
    __nv_bfloat16 l3 = __float2bfloat16_rn(v.w - __bfloat162float(h3));
    *(uint2*)(hi + (size_t)i * 4) = make_uint2(pack_bf2(h0, h1), pack_bf2(h2, h3));
    *(uint2*)(lo + (size_t)i * 4) = make_uint2(pack_bf2(l0, l1), pack_bf2(l2, l3));
}

__global__ __launch_bounds__(256)
void split_w4(const float* __restrict__ w0, const float* __restrict__ w1,
              const float* __restrict__ w2, const float* __restrict__ w3,
              __nv_bfloat16* __restrict__ hi, __nv_bfloat16* __restrict__ lo)
{
    const int n4 = (int)(WSZ / 4);
    int i = blockIdx.x * blockDim.x + threadIdx.x;
    int which = i / n4;
    int idx = i - which * n4;
    const float* src = (which == 0) ? w0 : (which == 1) ? w1
                     : (which == 2) ? w2 : w3;
    float4 v = *(const float4*)(src + (size_t)idx * 4);
    size_t o = (size_t)which * WSZ + (size_t)idx * 4;
    __nv_bfloat16 h0 = __float2bfloat16_rn(v.x);
    __nv_bfloat16 h1 = __float2bfloat16_rn(v.y);
    __nv_bfloat16 h2 = __float2bfloat16_rn(v.z);
    __nv_bfloat16 h3 = __float2bfloat16_rn(v.w);
    __nv_bfloat16 l0 = __float2bfloat16_rn(v.x - __bfloat162float(h0));
    __nv_bfloat16 l1 = __float2bfloat16_rn(v.y - __bfloat162float(h1));
    __nv_bfloat16 l2 = __float2bfloat16_rn(v.z - __bfloat162float(h2));
    __nv_bfloat16 l3 = __float2bfloat16_rn(v.w - __bfloat162float(h3));
    *(uint2*)(hi + o) = make_uint2(pack_bf2(h0, h1), pack_bf2(h2, h3));
    *(uint2*)(lo + o) = make_uint2(pack_bf2(l0, l1), pack_bf2(l2, l3));
}

// ===========================================================================
// Warp-MMA GEMM, double-buffered cp.async pipeline, pre-split bf16 inputs.
// MODE 0: C fp32 row-major (O-projection).
// MODE 1: fused QKV — blockIdx.z in {0,1,2} selects weight; epilogue emits
//         fp16 (Q scaled+split hi/lo, K split hi/lo, V single) in [B,H,T,D].
// ===========================================================================
#define STG 65536
#define GEMM_SMEM (2 * STG)

template<int MODE>
__global__ __launch_bounds__(256, 1)
void gemm_ps(const __nv_bfloat16* __restrict__ Ah,
             const __nv_bfloat16* __restrict__ Al,
             const __nv_bfloat16* __restrict__ Wh,
             const __nv_bfloat16* __restrict__ Wl,
             float* __restrict__ C,
             __half* __restrict__ qh, __half* __restrict__ ql,
             __half* __restrict__ kh, __half* __restrict__ kl,
             __half* __restrict__ vh)
{
    extern __shared__ __align__(1024) char smem[];
    const uint32_t sb = smem_addr_u32(smem);

    const int tid  = threadIdx.x;
    const int bcol = blockIdx.x;
    const int brow = blockIdx.y;
    const int z    = (MODE == 1) ? blockIdx.z : 0;
    const int warp = tid >> 5;
    const int lane = tid & 31;

    const int m0w = (warp >> 1) * 32;
    const int n0w = (warp & 1) * 64;

    const int ltile   = lane >> 3;
    const int within  = lane & 7;
    const int rowoff  = ((ltile & 1) << 3) + within;
    const int chalf   = (ltile >> 1) << 4;
    const int xorkey  = within << 4;

    const int crow[4] = { (tid + 0)   >> 3, (tid + 256) >> 3,
                          (tid + 512) >> 3, (tid + 768) >> 3 };
    const int ccol = (tid & 7) * 8;
    uint32_t cdst[4];
    #pragma unroll
    for (int j = 0; j < 4; ++j)
        cdst[j] = SMEM_SWIZZLE_128B((uint32_t)(crow[j] * 128 + ccol * 2));

    const __nv_bfloat16* pAh = Ah + (size_t)(brow * 128) * DM + ccol;
    const __nv_bfloat16* pAl = Al + (size_t)(brow * 128) * DM + ccol;
    const __nv_bfloat16* pBh = Wh + (size_t)z * WSZ + (size_t)(bcol * 128) * DM + ccol;
    const __nv_bfloat16* pBl = Wl + (size_t)z * WSZ + (size_t)(bcol * 128) * DM + ccol;

    auto prefetch = [&](int s) {
        const uint32_t b0 = sb + (uint32_t)(s & 1) * STG;
        const size_t koff = (size_t)s * 64;
        #pragma unroll
        for (int j = 0; j < 4; ++j) {
            const size_t ro = (size_t)crow[j] * DM + koff;
            cp_async16(b0 +         cdst[j], pAh + ro);
            cp_async16(b0 + 16384 + cdst[j], pAl + ro);
            cp_async16(b0 + 32768 + cdst[j], pBh + ro);
            cp_async16(b0 + 49152 + cdst[j], pBl + ro);
        }
        CP_COMMIT();
    };

    float acc[2][8][4];
    #pragma unroll
    for (int i = 0; i < 2; i++)
        #pragma unroll
        for (int j = 0; j < 8; j++)
            #pragma unroll
            for (int q = 0; q < 4; q++) acc[i][j][q] = 0.f;

    prefetch(0);

    for (int s = 0; s < 16; ++s) {
        if (s + 1 < 16) {
            prefetch(s + 1);
            asm volatile("cp.async.wait_group 1;" ::: "memory");
        } else {
            asm volatile("cp.async.wait_group 0;" ::: "memory");
        }
        __syncthreads();

        const uint32_t uAh = sb + (uint32_t)(s & 1) * STG;
        const uint32_t uAl = uAh + 16384;
        const uint32_t uBh = uAh + 32768;
        const uint32_t uBl = uAh + 49152;

        #pragma unroll
        for (int ks = 0; ks < 4; ++ks) {
            const uint32_t coff = (uint32_t)((ks * 32 + chalf) ^ xorkey);

            uint32_t ah[2][4], al[2][4];
            #pragma unroll
            for (int i = 0; i < 2; i++) {
                uint32_t ra = (uint32_t)((m0w + i * 16 + rowoff) * 128) + coff;
                ldmatrix_x4(ah[i][0], ah[i][1], ah[i][2], ah[i][3], uAh + ra);
                ldmatrix_x4(al[i][0], al[i][1], al[i][2], al[i][3], uAl + ra);
            }

            #pragma unroll
            for (int g = 0; g < 4; ++g) {
                uint32_t rb = (uint32_t)((n0w + g * 16 + rowoff) * 128) + coff;
                uint32_t bh[4], bl[4];
                ldmatrix_x4(bh[0], bh[1], bh[2], bh[3], uBh + rb);
                ldmatrix_x4(bl[0], bl[1], bl[2], bl[3], uBl + rb);
                #pragma unroll
                for (int jj = 0; jj < 2; ++jj) {
                    int j = g * 2 + jj;
                    #pragma unroll
                    for (int i = 0; i < 2; i++) {
                        mma_bf16(acc[i][j], ah[i], bh[jj], bh[2 + jj]);
                        mma_bf16(acc[i][j], ah[i], bl[jj], bl[2 + jj]);
                        mma_bf16(acc[i][j], al[i], bh[jj], bh[2 + jj]);
                    }
                }
            }
        }
        __syncthreads();
    }

    const int rfrag = lane >> 2;
    const int cfrag = (lane & 3) * 2;
    #pragma unroll
    for (int i = 0; i < 2; i++) {
        #pragma unroll
        for (int j = 0; j < 8; j++) {
            int m = brow * 128 + m0w + i * 16 + rfrag;
            int n = bcol * 128 + n0w + j * 8 + cfrag;
            if (MODE == 0) {
                *(float2*)(C + (size_t)m * DM + n) =
                    make_float2(acc[i][j][0], acc[i][j][1]);
                *(float2*)(C + (size_t)(m + 8) * DM + n) =
                    make_float2(acc[i][j][2], acc[i][j][3]);
            } else {
                int h = n >> 6, d = n & 63;
                int b0 = m >> 11, t0 = m & 2047;
                int m8 = m + 8;
                int b1 = m8 >> 11, t1 = m8 & 2047;
                size_t o0 = ((size_t)((b0 << 4) + h) * TT + t0) * HD + d;
                size_t o1 = ((size_t)((b1 << 4) + h) * TT + t1) * HD + d;
                float v00 = acc[i][j][0], v01 = acc[i][j][1];
                float v10 = acc[i][j][2], v11 = acc[i][j][3];
                if (z == 0) {
                    uint32_t hi0, lo0, hi1, lo1;
                    h_split2(v00 * QSCALE, v01 * QSCALE, hi0, lo0);
                    h_split2(v10 * QSCALE, v11 * QSCALE, hi1, lo1);
                    *(uint32_t*)(qh + o0) = hi0; *(uint32_t*)(ql + o0) = lo0;
                    *(uint32_t*)(qh + o1) = hi1; *(uint32_t*)(ql + o1) = lo1;
                } else if (z == 1) {
                    uint32_t hi0, lo0, hi1, lo1;
                    h_split2(v00, v01, hi0, lo0);
                    h_split2(v10, v11, hi1, lo1);
                    *(uint32_t*)(kh + o0) = hi0; *(uint32_t*)(kl + o0) = lo0;
                    *(uint32_t*)(kh + o1) = hi1; *(uint32_t*)(kl + o1) = lo1;
                } else {
                    *(uint32_t*)(vh + o0) = pack_h2(v00, v01);
                    *(uint32_t*)(vh + o1) = pack_h2(v10, v11);
                }
            }
        }
    }
}

// ===========================================================================
// Flash attention: all inputs pre-converted fp16; cp.async double-buffered
// K/V pipeline.  Smem: Qh 16K | Ql 16K | 2 x (Kh 8K | Kl 8K | Vh 8K) = 80K.
// ===========================================================================
#define KV_STG 24576
#define FLASH_SMEM (32768 + 2 * KV_STG)

__global__ __launch_bounds__(256, 1)
void flash_mma(const __half* __restrict__ gqh, const __half* __restrict__ gql,
               const __half* __restrict__ gkh, const __half* __restrict__ gkl,
               const __half* __restrict__ gvh,
               __nv_bfloat16* __restrict__ oh, __nv_bfloat16* __restrict__ ol)
{
    extern __shared__ __align__(1024) char smem[];
    const uint32_t sb = smem_addr_u32(smem);
    const uint32_t uQh = sb, uQl = sb + 16384;

    const int qb  = (int)gridDim.x - 1 - blockIdx.x;
    const int h   = blockIdx.y;
    const int b   = blockIdx.z;
    const int tid = threadIdx.x;
    const int warp = tid >> 5;
    const int lane = tid & 31;

    const int m0w = warp * 16;
    const int ltile  = lane >> 3;
    const int within = lane & 7;
    const int rowoff = ((ltile & 1) << 3) + within;
    const int chalf  = (ltile >> 1) << 4;
    const int xorkey = within << 4;
    const int g  = lane >> 2;
    const int t2 = lane & 3;

    const size_t bh = (size_t)(b * NH + h) * TT;
    const __half* qhp = gqh + (bh + (size_t)qb * 128) * HD;
    const __half* qlp = gql + (bh + (size_t)qb * 128) * HD;

    // Q copy: 1024 16B-chunks per buffer, 4 per thread each
    {
        #pragma unroll
        for (int it = 0; it < 4; ++it) {
            int chunk = tid + it * 256;
            int r  = chunk >> 3;
            int c8 = (chunk & 7) * 8;
            uint32_t dst = SMEM_SWIZZLE_128B((uint32_t)(r * 128 + c8 * 2));
            cp_async16(uQh + dst, qhp + (size_t)r * HD + c8);
            cp_async16(uQl + dst, qlp + (size_t)r * HD + c8);
        }
        CP_COMMIT();
    }

    const int jb_max = 2 * qb + 1;

    // K/V prefetch: 512 chunks per tensor per stage, 2 per thread each
    auto prefetch = [&](int jb) {
        const uint32_t b0 = sb + 32768 + (uint32_t)(jb & 1) * KV_STG;
        const __half* kbh = gkh + (bh + (size_t)jb * 64) * HD;
        const __half* kbl = gkl + (bh + (size_t)jb * 64) * HD;
        const __half* vb  = gvh + (bh + (size_t)jb * 64) * HD;
        #pragma unroll
        for (int it = 0; it < 2; ++it) {
            int chunk = tid + it * 256;
            int r  = chunk >> 3;
            int c8 = (chunk & 7) * 8;
            uint32_t dst = SMEM_SWIZZLE_128B((uint32_t)(r * 128 + c8 * 2));
            size_t ro = (size_t)r * HD + c8;
            cp_async16(b0 +         dst, kbh + ro);
            cp_async16(b0 + 8192  + dst, kbl + ro);
            cp_async16(b0 + 16384 + dst, vb  + ro);
        }
        CP_COMMIT();
    };

    prefetch(0);
    asm volatile("cp.async.wait_group 0;" ::: "memory");
    __syncthreads();

    // preload Q fragments (reused every KV block)
    uint32_t qf_h[4][4], qf_l[4][4];
    #pragma unroll
    for (int ks = 0; ks < 4; ++ks) {
        uint32_t coff = (uint32_t)((ks * 32 + chalf) ^ xorkey);
        uint32_t ra = (uint32_t)((m0w + rowoff) * 128) + coff;
        ldmatrix_x4(qf_h[ks][0], qf_h[ks][1], qf_h[ks][2], qf_h[ks][3], uQh + ra);
        ldmatrix_x4(qf_l[ks][0], qf_l[ks][1], qf_l[ks][2], qf_l[ks][3], uQl + ra);
    }

    float o[8][4];
    #pragma unroll
    for (int j = 0; j < 8; j++)
        #pragma unroll
        for (int q = 0; q < 4; q++) o[j][q] = 0.f;
    float m0 = -100000.f, m1 = -100000.f, l0 = 0.f, l1 = 0.f;

    const int r0g = qb * 128 + m0w + g;
    const int r1g = r0g + 8;

    for (int jb = 0; jb <= jb_max; ++jb) {
        if (jb < jb_max) {
            prefetch(jb + 1);
            asm volatile("cp.async.wait_group 1;" ::: "memory");
        } else {
            asm volatile("cp.async.wait_group 0;" ::: "memory");
        }
        __syncthreads();

        const uint32_t uKh = sb + 32768 + (uint32_t)(jb & 1) * KV_STG;
        const uint32_t uKl = uKh + 8192;
        const uint32_t uVh = uKh + 16384;

        // ---- S = Q @ K^T (fp16 hi/lo, 3 MMAs) ----
        float acc[8][4];
        #pragma unroll
        for (int j = 0; j < 8; j++)
            #pragma unroll
            for (int q = 0; q < 4; q++) acc[j][q] = 0.f;

        #pragma unroll
        for (int ks = 0; ks < 4; ++ks) {
            uint32_t coff = (uint32_t)((ks * 32 + chalf) ^ xorkey);
            #pragma unroll
            for (int g4 = 0; g4 < 4; ++g4) {
                uint32_t rb = (uint32_t)((g4 * 16 + rowoff) * 128) + coff;
                uint32_t khf[4], klf[4];
                ldmatrix_x4(khf[0], khf[1], khf[2], khf[3], uKh + rb);
                ldmatrix_x4(klf[0], klf[1], klf[2], klf[3], uKl + rb);
                #pragma unroll
                for (int jj = 0; jj < 2; ++jj) {
                    int j = g4 * 2 + jj;
                    mma_f16(acc[j], qf_h[ks], khf[jj], khf[2 + jj]);
                    mma_f16(acc[j], qf_h[ks], klf[jj], klf[2 + jj]);
                    mma_f16(acc[j], qf_l[ks], khf[jj], khf[2 + jj]);
                }
            }
        }

        if (jb >= 2 * qb) {
            #pragma unroll
            for (int j = 0; j < 8; j++) {
                int cb = jb * 64 + j * 8 + t2 * 2;
                if (cb     > r0g) acc[j][0] = -30000.f;
                if (cb + 1 > r0g) acc[j][1] = -30000.f;
                if (cb     > r1g) acc[j][2] = -30000.f;
                if (cb + 1 > r1g) acc[j][3] = -30000.f;
            }
        }

        float mx0 = -30000.f, mx1 = -30000.f;
        #pragma unroll
        for (int j = 0; j < 8; j++) {
            mx0 = fmaxf(mx0, fmaxf(acc[j][0], acc[j][1]));
            mx1 = fmaxf(mx1, fmaxf(acc[j][2], acc[j][3]));
        }
        mx0 = fmaxf(mx0, __shfl_xor_sync(0xffffffffu, mx0, 1));
        mx0 = fmaxf(mx0, __shfl_xor_sync(0xffffffffu, mx0, 2));
        mx1 = fmaxf(mx1, __shfl_xor_sync(0xffffffffu, mx1, 1));
        mx1 = fmaxf(mx1, __shfl_xor_sync(0xffffffffu, mx1, 2));

        float mn0 = fmaxf(m0, mx0), mn1 = fmaxf(m1, mx1);
        float a0 = fexp2(m0 - mn0), a1 = fexp2(m1 - mn1);
        m0 = mn0; m1 = mn1;

        float rs0 = 0.f, rs1 = 0.f;
        #pragma unroll
        for (int j = 0; j < 8; j++) {
            acc[j][0] = fexp2(acc[j][0] - mn0);
            acc[j][1] = fexp2(acc[j][1] - mn0);
            acc[j][2] = fexp2(acc[j][2] - mn1);
            acc[j][3] = fexp2(acc[j][3] - mn1);
            rs0 += acc[j][0] + acc[j][1];
            rs1 += acc[j][2] + acc[j][3];
        }
        rs0 += __shfl_xor_sync(0xffffffffu, rs0, 1);
        rs0 += __shfl_xor_sync(0xffffffffu, rs0, 2);
        rs1 += __shfl_xor_sync(0xffffffffu, rs1, 1);
        rs1 += __shfl_xor_sync(0xffffffffu, rs1, 2);
        l0 = l0 * a0 + rs0;
        l1 = l1 * a1 + rs1;

        #pragma unroll
        for (int j = 0; j < 8; j++) {
            o[j][0] *= a0; o[j][1] *= a0;
            o[j][2] *= a1; o[j][3] *= a1;
        }

        uint32_t pf[4][4];
        #pragma unroll
        for (int j0 = 0; j0 < 4; ++j0) {
            pf[j0][0] = pack_h2(acc[2*j0][0],   acc[2*j0][1]);
            pf[j0][1] = pack_h2(acc[2*j0][2],   acc[2*j0][3]);
            pf[j0][2] = pack_h2(acc[2*j0+1][0], acc[2*j0+1][1]);
            pf[j0][3] = pack_h2(acc[2*j0+1][2], acc[2*j0+1][3]);
        }

        #pragma unroll
        for (int s0t = 0; s0t < 4; ++s0t) {
            #pragma unroll
            for (int d0t = 0; d0t < 4; ++d0t) {
                uint32_t addr = uVh + (uint32_t)((s0t * 16 + rowoff) * 128)
                              + (uint32_t)((d0t * 32 + chalf) ^ xorkey);
                uint32_t w0, w1, w2, w3;
                ldmatrix_x4_trans(w0, w1, w2, w3, addr);
                mma_f16(o[d0t * 2],     pf[s0t], w0, w1);
                mma_f16(o[d0t * 2 + 1], pf[s0t], w2, w3);
            }
        }
        __syncthreads();   // stage buffer free for prefetch(jb+2)
    }

    float inv0 = 1.f / l0, inv1 = 1.f / l1;
    const int tg0 = qb * 128 + m0w + g;
    const int tg1 = tg0 + 8;
    #pragma unroll
    for (int j = 0; j < 8; j++) {
        int d = h * HD + j * 8 + t2 * 2;
        size_t off0 = (size_t)(b * TT + tg0) * DM + d;
        size_t off1 = (size_t)(b * TT + tg1) * DM + d;
        float v00 = o[j][0] * inv0, v01 = o[j][1] * inv0;
        float v10 = o[j][2] * inv1, v11 = o[j][3] * inv1;
        __nv_bfloat16 h00 = __float2bfloat16_rn(v00);
        __nv_bfloat16 h01 = __float2bfloat16_rn(v01);
        __nv_bfloat16 h10 = __float2bfloat16_rn(v10);
        __nv_bfloat16 h11 = __float2bfloat16_rn(v11);
        *(uint32_t*)(oh + off0) = pack_bf2(h00, h01);
        *(uint32_t*)(oh + off1) = pack_bf2(h10, h11);
        *(uint32_t*)(ol + off0) = pack_bf2(
            __float2bfloat16_rn(v00 - __bfloat162float(h00)),
            __float2bfloat16_rn(v01 - __bfloat162float(h01)));
        *(uint32_t*)(ol + off1) = pack_bf2(
            __float2bfloat16_rn(v10 - __bfloat162float(h10)),
            __float2bfloat16_rn(v11 - __bfloat162float(h11)));
    }
}

// ---------------------------------------------------------------------------
extern "C" void kernel_launch(void* const* d_in, const int* in_sizes, int n_in,
                              void* d_out, int out_size)
{
    const float* x  = (const float*)d_in[0];
    const float* Wq = (const float*)d_in[1];
    const float* Wk = (const float*)d_in[2];
    const float* Wv = (const float*)d_in[3];
    const float* Wo = (const float*)d_in[4];
    float* out = (float*)d_out;

    __half *qh, *ql, *kh, *kl, *vh;
    __nv_bfloat16 *xh, *xl, *wh, *wl, *ah, *al;
    cudaGetSymbolAddress((void**)&qh, g_qh);
    cudaGetSymbolAddress((void**)&ql, g_ql);
    cudaGetSymbolAddress((void**)&kh, g_kh);
    cudaGetSymbolAddress((void**)&kl, g_kl);
    cudaGetSymbolAddress((void**)&vh, g_vh);
    cudaGetSymbolAddress((void**)&xh, g_xh);
    cudaGetSymbolAddress((void**)&xl, g_xl);
    cudaGetSymbolAddress((void**)&wh, g_wh);
    cudaGetSymbolAddress((void**)&wl, g_wl);
    cudaGetSymbolAddress((void**)&ah, g_ah);
    cudaGetSymbolAddress((void**)&al, g_al);

    cudaFuncSetAttribute(gemm_ps<0>, cudaFuncAttributeMaxDynamicSharedMemorySize, GEMM_SMEM);
    cudaFuncSetAttribute(gemm_ps<1>, cudaFuncAttributeMaxDynamicSharedMemorySize, GEMM_SMEM);
    cudaFuncSetAttribute(flash_mma,  cudaFuncAttributeMaxDynamicSharedMemorySize, FLASH_SMEM);

    split_f32<<<(MM * DM / 4 + 255) / 256, 256>>>(x, xh, xl, MM * DM / 4);
    split_w4<<<(int)(4 * WSZ / 4 + 255) / 256, 256>>>(Wq, Wk, Wv, Wo, wh, wl);

    // fused QKV projections (z selects weight + epilogue)
    gemm_ps<1><<<dim3(DM / 128, MM / 128, 3), 256, GEMM_SMEM>>>(
        xh, xl, wh, wl, nullptr, qh, ql, kh, kl, vh);

    flash_mma<<<dim3(TT / 128, NH, BB), 256, FLASH_SMEM>>>(qh, ql, kh, kl, vh, ah, al);

    gemm_ps<0><<<dim3(DM / 128, MM / 128), 256, GEMM_SMEM>>>(
        ah, al, wh + 3 * WSZ, wl + 3 * WSZ, out, nullptr, nullptr, nullptr, nullptr, nullptr);
}